// round 14
// baseline (speedup 1.0000x reference)
#include <cuda_runtime.h>
#include <math.h>

// Problem dims (fixed by reference)
#define BB 8
#define TT 2048
#define DD 1024
#define HD 64
#define MM 64
#define SSZ (TT + MM)          // 2112 keys/values per batch
#define BT (BB * TT)           // 16384 query rows total

// d^-0.5 * log2(e): logits produced directly in log2 domain
#define SCALE_Q 0.18033688011112042f

// Scratch (allocation-free rule: __device__ globals)
__device__ float g_q[BT * HD];          // prescaled by d^-0.5*log2e
__device__ float g_k[BB * SSZ * HD];
__device__ float g_v[BB * SSZ * HD];

// ---------------------------------------------------------------------------
// Helpers
// ---------------------------------------------------------------------------
__device__ __forceinline__ unsigned tf32u(float x) {
    unsigned u;
    asm("cvt.rna.tf32.f32 %0, %1;" : "=r"(u) : "f"(x));
    return u;
}
__device__ __forceinline__ float tf32r(float x) {
    return __uint_as_float(tf32u(x));
}
__device__ __forceinline__ void mma8(float* c,
                                     unsigned a0, unsigned a1, unsigned a2, unsigned a3,
                                     unsigned b0, unsigned b1) {
    asm volatile(
        "mma.sync.aligned.m16n8k8.row.col.f32.tf32.tf32.f32 "
        "{%0,%1,%2,%3},{%4,%5,%6,%7},{%8,%9},{%0,%1,%2,%3};"
        : "+f"(c[0]), "+f"(c[1]), "+f"(c[2]), "+f"(c[3])
        : "r"(a0), "r"(a1), "r"(a2), "r"(a3), "r"(b0), "r"(b1));
}

// 2^y via MUFU (single instruction, separate pipe). rel err ~1e-6.
__device__ __forceinline__ float exp2a(float y) {
    float r;
    asm("ex2.approx.f32 %0, %1;" : "=f"(r) : "f"(y));
    return r;
}

__device__ __forceinline__ void cp16(void* smem_dst, const void* gmem_src) {
    unsigned s = (unsigned)__cvta_generic_to_shared(smem_dst);
    asm volatile("cp.async.cg.shared.global [%0], [%1], 16;"
                 :: "r"(s), "l"(gmem_src));
}
#define CP_COMMIT() asm volatile("cp.async.commit_group;" ::: "memory")
#define CP_WAIT0()  asm volatile("cp.async.wait_group 0;" ::: "memory")

// ---------------------------------------------------------------------------
// Kernel 1: layernorm(c_emb) -> broadcast (tf32-rounded) into g_k/g_v tails
// ---------------------------------------------------------------------------
__global__ void ln_kernel(const float* __restrict__ c_emb,
                          const float* __restrict__ gamma,
                          const float* __restrict__ beta) {
    int m = blockIdx.x;
    int t = threadIdx.x;
    __shared__ float red[64];

    float v = c_emb[m * HD + t];
    red[t] = v;
    __syncthreads();
    for (int off = 32; off > 0; off >>= 1) {
        if (t < off) red[t] += red[t + off];
        __syncthreads();
    }
    float mu = red[0] * (1.0f / HD);
    __syncthreads();
    float dv = v - mu;
    red[t] = dv * dv;
    __syncthreads();
    for (int off = 32; off > 0; off >>= 1) {
        if (t < off) red[t] += red[t + off];
        __syncthreads();
    }
    float var = red[0] * (1.0f / HD);
    float y = tf32r(dv * rsqrtf(var + 1e-5f) * gamma[t] + beta[t]);

    #pragma unroll
    for (int b = 0; b < BB; b++) {
        int idx = ((b * SSZ) + TT + m) * HD + t;
        g_k[idx] = y;
        g_v[idx] = y;
    }
}

// ---------------------------------------------------------------------------
// Kernel 2: fused QKV projection v2 (R12, proven). Tile 128(M) x 192(N),
// K-chunk 32; grid = 128 CTAs. 8 warps as 4(M: 32 rows) x 2(N: 96 cols);
// B-fragments reused across 2 M-tiles. Register prefetch of next K-chunk.
// ---------------------------------------------------------------------------
#define XS_ST 36
#define WS_ST 196
__global__ __launch_bounds__(256) void qkv_kernel(
    const float* __restrict__ x,
    const float* __restrict__ Wq,
    const float* __restrict__ Wk,
    const float* __restrict__ Wv) {

    __shared__ float xs[128][XS_ST];     // 18.4 KB
    __shared__ float ws[32][WS_ST];      // 25.1 KB

    int tid = threadIdx.x;
    int lane = tid & 31;
    int wid = tid >> 5;
    int wm = wid & 3;                    // 32-row group
    int wn = wid >> 2;                   // 96-col group
    int g = lane >> 2;
    int t = lane & 3;
    int row0 = blockIdx.x * 128;

    float acc[2][12][4];
    #pragma unroll
    for (int h = 0; h < 2; h++)
        #pragma unroll
        for (int n = 0; n < 12; n++)
            #pragma unroll
            for (int i = 0; i < 4; i++) acc[h][n][i] = 0.0f;

    float4 xr[4], wqr[2], wkr[2], wvr[2];

    #pragma unroll
    for (int i = 0; i < 4; i++) {
        int idx = tid + i * 256;
        int r = idx >> 3;
        int q = idx & 7;
        xr[i] = *(const float4*)&x[(size_t)(row0 + r) * DD + q * 4];
    }
    #pragma unroll
    for (int i = 0; i < 2; i++) {
        int idx = tid + i * 256;
        int r = idx >> 4;
        int q = idx & 15;
        wqr[i] = *(const float4*)&Wq[(size_t)r * HD + q * 4];
        wkr[i] = *(const float4*)&Wk[(size_t)r * HD + q * 4];
        wvr[i] = *(const float4*)&Wv[(size_t)r * HD + q * 4];
    }

    for (int k0 = 0; k0 < DD; k0 += 32) {
        #pragma unroll
        for (int i = 0; i < 4; i++) {
            int idx = tid + i * 256;
            int r = idx >> 3;
            int q = idx & 7;
            xs[r][q * 4 + 0] = tf32r(xr[i].x);
            xs[r][q * 4 + 1] = tf32r(xr[i].y);
            xs[r][q * 4 + 2] = tf32r(xr[i].z);
            xs[r][q * 4 + 3] = tf32r(xr[i].w);
        }
        #pragma unroll
        for (int i = 0; i < 2; i++) {
            int idx = tid + i * 256;
            int r = idx >> 4;
            int q = idx & 15;
            int c = q * 4;
            ws[r][c + 0] = tf32r(wqr[i].x); ws[r][c + 1] = tf32r(wqr[i].y);
            ws[r][c + 2] = tf32r(wqr[i].z); ws[r][c + 3] = tf32r(wqr[i].w);
            ws[r][64 + c + 0] = tf32r(wkr[i].x); ws[r][64 + c + 1] = tf32r(wkr[i].y);
            ws[r][64 + c + 2] = tf32r(wkr[i].z); ws[r][64 + c + 3] = tf32r(wkr[i].w);
            ws[r][128 + c + 0] = tf32r(wvr[i].x); ws[r][128 + c + 1] = tf32r(wvr[i].y);
            ws[r][128 + c + 2] = tf32r(wvr[i].z); ws[r][128 + c + 3] = tf32r(wvr[i].w);
        }
        __syncthreads();

        if (k0 + 32 < DD) {
            int kn = k0 + 32;
            #pragma unroll
            for (int i = 0; i < 4; i++) {
                int idx = tid + i * 256;
                int r = idx >> 3;
                int q = idx & 7;
                xr[i] = *(const float4*)&x[(size_t)(row0 + r) * DD + kn + q * 4];
            }
            #pragma unroll
            for (int i = 0; i < 2; i++) {
                int idx = tid + i * 256;
                int r = idx >> 4;
                int q = idx & 15;
                wqr[i] = *(const float4*)&Wq[(size_t)(kn + r) * HD + q * 4];
                wkr[i] = *(const float4*)&Wk[(size_t)(kn + r) * HD + q * 4];
                wvr[i] = *(const float4*)&Wv[(size_t)(kn + r) * HD + q * 4];
            }
        }

        #pragma unroll
        for (int kk = 0; kk < 4; kk++) {
            int kb = kk * 8;
            unsigned a[2][4];
            #pragma unroll
            for (int h = 0; h < 2; h++) {
                int rr = wm * 32 + h * 16 + g;
                a[h][0] = __float_as_uint(xs[rr][kb + t]);
                a[h][1] = __float_as_uint(xs[rr + 8][kb + t]);
                a[h][2] = __float_as_uint(xs[rr][kb + t + 4]);
                a[h][3] = __float_as_uint(xs[rr + 8][kb + t + 4]);
            }
            #pragma unroll
            for (int n = 0; n < 12; n++) {
                int nc = wn * 96 + n * 8;
                unsigned b0 = __float_as_uint(ws[kb + t][nc + g]);
                unsigned b1 = __float_as_uint(ws[kb + t + 4][nc + g]);
                mma8(acc[0][n], a[0][0], a[0][1], a[0][2], a[0][3], b0, b1);
                mma8(acc[1][n], a[1][0], a[1][1], a[1][2], a[1][3], b0, b1);
            }
        }
        __syncthreads();
    }

    #pragma unroll
    for (int h = 0; h < 2; h++) {
        int r0 = row0 + wm * 32 + h * 16 + g;
        #pragma unroll
        for (int n = 0; n < 12; n++) {
            int nc = wn * 96 + n * 8;
            int mat = nc >> 6;
            int lc = (nc & 63) + 2 * t;
            #pragma unroll
            for (int hh = 0; hh < 2; hh++) {
                int r = r0 + hh * 8;
                float v0 = acc[h][n][hh * 2 + 0];
                float v1 = acc[h][n][hh * 2 + 1];
                if (mat == 0) {
                    float2 o = make_float2(tf32r(v0 * SCALE_Q), tf32r(v1 * SCALE_Q));
                    *(float2*)&g_q[(size_t)r * HD + lc] = o;
                } else {
                    int b = r >> 11;
                    int rr = r & 2047;
                    float2 o = make_float2(tf32r(v0), tf32r(v1));
                    if (mat == 1) *(float2*)&g_k[((size_t)b * SSZ + rr) * HD + lc] = o;
                    else          *(float2*)&g_v[((size_t)b * SSZ + rr) * HD + lc] = o;
                }
            }
        }
    }
}

// ---------------------------------------------------------------------------
// Kernel 3: flash attention v4. 128 queries/CTA, 4 warps x 32 rows each.
// Q fragments hoisted to registers (qf[2][8][4]); the Q staging buffer is
// reused as the P buffer (warp-private rows -> no cross-warp hazard).
// Softmax exp on MUFU; S in registers; 1 barrier per tile.
// ---------------------------------------------------------------------------
#define TP2 68                               // stride = 4 (mod 32)
#define KVB (64 * TP2)                       // one K or V buffer (floats)
#define ATTN_SMEM_FLOATS (128 * TP2 + 4 * KVB)
#define ATTN_SMEM_BYTES  (ATTN_SMEM_FLOATS * 4)

__global__ __launch_bounds__(128, 1) void attn_kernel(float* __restrict__ out) {
    extern __shared__ float sm[];
    float* ps = sm;                          // [128][TP2]: Q staging, then P
    float* ks = sm + 128 * TP2;              // 2 x [64][TP2]
    float* vs = ks + 2 * KVB;                // 2 x [64][TP2]

    int tid = threadIdx.x;
    int lane = tid & 31;
    int w = tid >> 5;                        // warp id: rows w*32..w*32+31
    int g = lane >> 2;
    int t = lane & 3;
    int b = blockIdx.y;
    int q0 = blockIdx.x * 128;
    int r0 = w * 32;

    // Prologue: async-load K/V tile 0 into buffer 0 (overlaps Q staging)
    #pragma unroll
    for (int it = 0; it < 8; it++) {
        int idx = tid + it * 128;
        int r = idx >> 4;
        int q = idx & 15;
        size_t src = ((size_t)b * SSZ + r) * HD + q * 4;
        cp16(ks + r * TP2 + q * 4, &g_k[src]);
        cp16(vs + r * TP2 + q * 4, &g_v[src]);
    }
    CP_COMMIT();

    // Stage Q 128x64 (coalesced), then hoist this warp's fragments to regs
    #pragma unroll
    for (int i = 0; i < 16; i++) {
        int idx = tid + i * 128;
        int r = idx >> 4;
        int q = idx & 15;
        float4 v = *(const float4*)&g_q[((size_t)b * TT + q0 + r) * HD + q * 4];
        *(float4*)&ps[r * TP2 + q * 4] = v;
    }
    __syncthreads();
    unsigned qf[2][8][4];
    #pragma unroll
    for (int h = 0; h < 2; h++) {
        int rr = r0 + h * 16 + g;
        #pragma unroll
        for (int kk = 0; kk < 8; kk++) {
            int kb = kk * 8;
            qf[h][kk][0] = __float_as_uint(ps[rr * TP2 + kb + t]);
            qf[h][kk][1] = __float_as_uint(ps[(rr + 8) * TP2 + kb + t]);
            qf[h][kk][2] = __float_as_uint(ps[rr * TP2 + kb + t + 4]);
            qf[h][kk][3] = __float_as_uint(ps[(rr + 8) * TP2 + kb + t + 4]);
        }
    }
    // ps rows r0..r0+31 are warp-private from here (reused for P)

    // Row stats: h=0 -> rows r0+g, r0+g+8; h=1 -> rows r0+16+g, r0+16+g+8
    float m[4] = {-1e30f, -1e30f, -1e30f, -1e30f};
    float l[4] = {0.0f, 0.0f, 0.0f, 0.0f};
    float acc[2][8][4];
    #pragma unroll
    for (int h = 0; h < 2; h++)
        #pragma unroll
        for (int n = 0; n < 8; n++)
            #pragma unroll
            for (int i = 0; i < 4; i++) acc[h][n][i] = 0.0f;

    for (int ti = 0; ti < 33; ti++) {
        CP_WAIT0();
        __syncthreads();   // tile ti visible; everyone done with prev iter

        if (ti < 32) {
            int s0 = (ti + 1) * 64;
            float* kb_ = ks + ((ti + 1) & 1) * KVB;
            float* vb_ = vs + ((ti + 1) & 1) * KVB;
            #pragma unroll
            for (int it = 0; it < 8; it++) {
                int idx = tid + it * 128;
                int r = idx >> 4;
                int q = idx & 15;
                size_t src = ((size_t)b * SSZ + s0 + r) * HD + q * 4;
                cp16(kb_ + r * TP2 + q * 4, &g_k[src]);
                cp16(vb_ + r * TP2 + q * 4, &g_v[src]);
            }
            CP_COMMIT();
        }

        const float* kcur = ks + (ti & 1) * KVB;
        const float* vcur = vs + (ti & 1) * KVB;

        // Phase A: S = Q * K^T  (warp: 32 rows x 64 cols; Q in registers)
        float sc[2][8][4];
        #pragma unroll
        for (int h = 0; h < 2; h++)
            #pragma unroll
            for (int n = 0; n < 8; n++)
                #pragma unroll
                for (int i = 0; i < 4; i++) sc[h][n][i] = 0.0f;
        #pragma unroll
        for (int kk = 0; kk < 8; kk++) {
            int kb = kk * 8;
            #pragma unroll
            for (int n = 0; n < 8; n++) {
                unsigned b0 = __float_as_uint(kcur[(n * 8 + g) * TP2 + kb + t]);
                unsigned b1 = __float_as_uint(kcur[(n * 8 + g) * TP2 + kb + t + 4]);
                mma8(sc[0][n], qf[0][kk][0], qf[0][kk][1], qf[0][kk][2], qf[0][kk][3], b0, b1);
                mma8(sc[1][n], qf[1][kk][0], qf[1][kk][1], qf[1][kk][2], qf[1][kk][3], b0, b1);
            }
        }

        // Softmax (registers + shfl; exp on MUFU), then stash P
        #pragma unroll
        for (int h = 0; h < 2; h++) {
            float mx0 = -1e30f, mx1 = -1e30f;
            #pragma unroll
            for (int n = 0; n < 8; n++) {
                mx0 = fmaxf(mx0, fmaxf(sc[h][n][0], sc[h][n][1]));
                mx1 = fmaxf(mx1, fmaxf(sc[h][n][2], sc[h][n][3]));
            }
            mx0 = fmaxf(mx0, __shfl_xor_sync(0xffffffffu, mx0, 1));
            mx0 = fmaxf(mx0, __shfl_xor_sync(0xffffffffu, mx0, 2));
            mx1 = fmaxf(mx1, __shfl_xor_sync(0xffffffffu, mx1, 1));
            mx1 = fmaxf(mx1, __shfl_xor_sync(0xffffffffu, mx1, 2));
            float mn0 = fmaxf(m[2 * h], mx0);
            float mn1 = fmaxf(m[2 * h + 1], mx1);
            float f0 = exp2a(m[2 * h] - mn0);
            float f1 = exp2a(m[2 * h + 1] - mn1);
            float s0 = 0.0f, s1 = 0.0f;
            #pragma unroll
            for (int n = 0; n < 8; n++) {
                sc[h][n][0] = tf32r(exp2a(sc[h][n][0] - mn0)); s0 += sc[h][n][0];
                sc[h][n][1] = tf32r(exp2a(sc[h][n][1] - mn0)); s0 += sc[h][n][1];
                sc[h][n][2] = tf32r(exp2a(sc[h][n][2] - mn1)); s1 += sc[h][n][2];
                sc[h][n][3] = tf32r(exp2a(sc[h][n][3] - mn1)); s1 += sc[h][n][3];
            }
            s0 += __shfl_xor_sync(0xffffffffu, s0, 1);
            s0 += __shfl_xor_sync(0xffffffffu, s0, 2);
            s1 += __shfl_xor_sync(0xffffffffu, s1, 1);
            s1 += __shfl_xor_sync(0xffffffffu, s1, 2);
            l[2 * h]     = l[2 * h] * f0 + s0;
            l[2 * h + 1] = l[2 * h + 1] * f1 + s1;
            m[2 * h]     = mn0;
            m[2 * h + 1] = mn1;
            #pragma unroll
            for (int n = 0; n < 8; n++) {
                acc[h][n][0] *= f0; acc[h][n][1] *= f0;
                acc[h][n][2] *= f1; acc[h][n][3] *= f1;
            }
            int rr = r0 + h * 16 + g;
            #pragma unroll
            for (int n = 0; n < 8; n++) {
                *(float2*)&ps[rr * TP2 + n * 8 + 2 * t] =
                    make_float2(sc[h][n][0], sc[h][n][1]);
                *(float2*)&ps[(rr + 8) * TP2 + n * 8 + 2 * t] =
                    make_float2(sc[h][n][2], sc[h][n][3]);
            }
        }
        __syncwarp();

        // Phase C: O += P * V  (warp: 32 rows x 64 cols; V frags reused 2x)
        #pragma unroll
        for (int kk = 0; kk < 8; kk++) {
            int kb = kk * 8;
            unsigned a[2][4];
            #pragma unroll
            for (int h = 0; h < 2; h++) {
                int rr = r0 + h * 16 + g;
                a[h][0] = __float_as_uint(ps[rr * TP2 + kb + t]);
                a[h][1] = __float_as_uint(ps[(rr + 8) * TP2 + kb + t]);
                a[h][2] = __float_as_uint(ps[rr * TP2 + kb + t + 4]);
                a[h][3] = __float_as_uint(ps[(rr + 8) * TP2 + kb + t + 4]);
            }
            #pragma unroll
            for (int n = 0; n < 8; n++) {
                unsigned b0 = __float_as_uint(vcur[(kb + t) * TP2 + n * 8 + g]);
                unsigned b1 = __float_as_uint(vcur[(kb + t + 4) * TP2 + n * 8 + g]);
                mma8(acc[0][n], a[0][0], a[0][1], a[0][2], a[0][3], b0, b1);
                mma8(acc[1][n], a[1][0], a[1][1], a[1][2], a[1][3], b0, b1);
            }
        }
        // next-iter __syncthreads guards K/V buffer and P-slice reuse
    }

    // Epilogue: normalize by l and store
    #pragma unroll
    for (int h = 0; h < 2; h++) {
        int ra = q0 + r0 + h * 16 + g;
        int rb = ra + 8;
        float ia = 1.0f / l[2 * h];
        float ib = 1.0f / l[2 * h + 1];
        #pragma unroll
        for (int n = 0; n < 8; n++) {
            int col = n * 8 + 2 * t;
            *(float2*)&out[((size_t)b * TT + ra) * HD + col] =
                make_float2(acc[h][n][0] * ia, acc[h][n][1] * ia);
            *(float2*)&out[((size_t)b * TT + rb) * HD + col] =
                make_float2(acc[h][n][2] * ib, acc[h][n][3] * ib);
        }
    }
}

// ---------------------------------------------------------------------------
extern "C" void kernel_launch(void* const* d_in, const int* in_sizes, int n_in,
                              void* d_out, int out_size) {
    const float* x      = (const float*)d_in[0];  // [8,2048,1024]
    const float* c_emb  = (const float*)d_in[1];  // [64,64]
    const float* Wq     = (const float*)d_in[2];  // [1024,64]
    const float* Wk     = (const float*)d_in[3];
    const float* Wv     = (const float*)d_in[4];
    const float* gamma  = (const float*)d_in[5];  // [64]
    const float* beta   = (const float*)d_in[6];  // [64]
    float* out          = (float*)d_out;          // [8,2048,64]

    (void)in_sizes; (void)n_in; (void)out_size;

    cudaFuncSetAttribute(attn_kernel,
                         cudaFuncAttributeMaxDynamicSharedMemorySize,
                         ATTN_SMEM_BYTES);

    ln_kernel<<<MM, 64>>>(c_emb, gamma, beta);
    qkv_kernel<<<BT / 128, 256>>>(x, Wq, Wk, Wv);
    dim3 agrid(TT / 128, BB);
    attn_kernel<<<agrid, 128, ATTN_SMEM_BYTES>>>(out);
}

// round 16
// speedup vs baseline: 1.0631x; 1.0631x over previous
#include <cuda_runtime.h>
#include <math.h>

// Problem dims (fixed by reference)
#define BB 8
#define TT 2048
#define DD 1024
#define HD 64
#define MM 64
#define SSZ (TT + MM)          // 2112 keys/values per batch
#define BT (BB * TT)           // 16384 query rows total

// d^-0.5 * log2(e): logits produced directly in log2 domain
#define SCALE_Q 0.18033688011112042f

// Scratch (allocation-free rule: __device__ globals)
__device__ float g_q[BT * HD];          // prescaled by d^-0.5*log2e
__device__ float g_k[BB * SSZ * HD];
__device__ float g_v[BB * SSZ * HD];

// ---------------------------------------------------------------------------
// Helpers
// ---------------------------------------------------------------------------
__device__ __forceinline__ unsigned tf32u(float x) {
    unsigned u;
    asm("cvt.rna.tf32.f32 %0, %1;" : "=r"(u) : "f"(x));
    return u;
}
__device__ __forceinline__ float tf32r(float x) {
    return __uint_as_float(tf32u(x));
}
__device__ __forceinline__ void mma8(float* c,
                                     unsigned a0, unsigned a1, unsigned a2, unsigned a3,
                                     unsigned b0, unsigned b1) {
    asm volatile(
        "mma.sync.aligned.m16n8k8.row.col.f32.tf32.tf32.f32 "
        "{%0,%1,%2,%3},{%4,%5,%6,%7},{%8,%9},{%0,%1,%2,%3};"
        : "+f"(c[0]), "+f"(c[1]), "+f"(c[2]), "+f"(c[3])
        : "r"(a0), "r"(a1), "r"(a2), "r"(a3), "r"(b0), "r"(b1));
}

// 2^y via MUFU (single instruction, separate pipe). rel err ~1e-6.
__device__ __forceinline__ float exp2a(float y) {
    float r;
    asm("ex2.approx.f32 %0, %1;" : "=f"(r) : "f"(y));
    return r;
}

__device__ __forceinline__ void cp16(void* smem_dst, const void* gmem_src) {
    unsigned s = (unsigned)__cvta_generic_to_shared(smem_dst);
    asm volatile("cp.async.cg.shared.global [%0], [%1], 16;"
                 :: "r"(s), "l"(gmem_src));
}
#define CP_COMMIT() asm volatile("cp.async.commit_group;" ::: "memory")
#define CP_WAIT0()  asm volatile("cp.async.wait_group 0;" ::: "memory")

// ---------------------------------------------------------------------------
// Kernel 1: layernorm(c_emb) -> broadcast (tf32-rounded) into g_k/g_v tails
// ---------------------------------------------------------------------------
__global__ void ln_kernel(const float* __restrict__ c_emb,
                          const float* __restrict__ gamma,
                          const float* __restrict__ beta) {
    int m = blockIdx.x;
    int t = threadIdx.x;
    __shared__ float red[64];

    float v = c_emb[m * HD + t];
    red[t] = v;
    __syncthreads();
    for (int off = 32; off > 0; off >>= 1) {
        if (t < off) red[t] += red[t + off];
        __syncthreads();
    }
    float mu = red[0] * (1.0f / HD);
    __syncthreads();
    float dv = v - mu;
    red[t] = dv * dv;
    __syncthreads();
    for (int off = 32; off > 0; off >>= 1) {
        if (t < off) red[t] += red[t + off];
        __syncthreads();
    }
    float var = red[0] * (1.0f / HD);
    float y = tf32r(dv * rsqrtf(var + 1e-5f) * gamma[t] + beta[t]);

    #pragma unroll
    for (int b = 0; b < BB; b++) {
        int idx = ((b * SSZ) + TT + m) * HD + t;
        g_k[idx] = y;
        g_v[idx] = y;
    }
}

// ---------------------------------------------------------------------------
// Kernel 2: fused QKV projection v2 (R12, proven). Tile 128(M) x 192(N),
// K-chunk 32; grid = 128 CTAs. 8 warps as 4(M: 32 rows) x 2(N: 96 cols);
// B-fragments reused across 2 M-tiles. Register prefetch of next K-chunk.
// ---------------------------------------------------------------------------
#define XS_ST 36
#define WS_ST 196
__global__ __launch_bounds__(256) void qkv_kernel(
    const float* __restrict__ x,
    const float* __restrict__ Wq,
    const float* __restrict__ Wk,
    const float* __restrict__ Wv) {

    __shared__ float xs[128][XS_ST];     // 18.4 KB
    __shared__ float ws[32][WS_ST];      // 25.1 KB

    int tid = threadIdx.x;
    int lane = tid & 31;
    int wid = tid >> 5;
    int wm = wid & 3;                    // 32-row group
    int wn = wid >> 2;                   // 96-col group
    int g = lane >> 2;
    int t = lane & 3;
    int row0 = blockIdx.x * 128;

    float acc[2][12][4];
    #pragma unroll
    for (int h = 0; h < 2; h++)
        #pragma unroll
        for (int n = 0; n < 12; n++)
            #pragma unroll
            for (int i = 0; i < 4; i++) acc[h][n][i] = 0.0f;

    float4 xr[4], wqr[2], wkr[2], wvr[2];

    #pragma unroll
    for (int i = 0; i < 4; i++) {
        int idx = tid + i * 256;
        int r = idx >> 3;
        int q = idx & 7;
        xr[i] = *(const float4*)&x[(size_t)(row0 + r) * DD + q * 4];
    }
    #pragma unroll
    for (int i = 0; i < 2; i++) {
        int idx = tid + i * 256;
        int r = idx >> 4;
        int q = idx & 15;
        wqr[i] = *(const float4*)&Wq[(size_t)r * HD + q * 4];
        wkr[i] = *(const float4*)&Wk[(size_t)r * HD + q * 4];
        wvr[i] = *(const float4*)&Wv[(size_t)r * HD + q * 4];
    }

    for (int k0 = 0; k0 < DD; k0 += 32) {
        #pragma unroll
        for (int i = 0; i < 4; i++) {
            int idx = tid + i * 256;
            int r = idx >> 3;
            int q = idx & 7;
            xs[r][q * 4 + 0] = tf32r(xr[i].x);
            xs[r][q * 4 + 1] = tf32r(xr[i].y);
            xs[r][q * 4 + 2] = tf32r(xr[i].z);
            xs[r][q * 4 + 3] = tf32r(xr[i].w);
        }
        #pragma unroll
        for (int i = 0; i < 2; i++) {
            int idx = tid + i * 256;
            int r = idx >> 4;
            int q = idx & 15;
            int c = q * 4;
            ws[r][c + 0] = tf32r(wqr[i].x); ws[r][c + 1] = tf32r(wqr[i].y);
            ws[r][c + 2] = tf32r(wqr[i].z); ws[r][c + 3] = tf32r(wqr[i].w);
            ws[r][64 + c + 0] = tf32r(wkr[i].x); ws[r][64 + c + 1] = tf32r(wkr[i].y);
            ws[r][64 + c + 2] = tf32r(wkr[i].z); ws[r][64 + c + 3] = tf32r(wkr[i].w);
            ws[r][128 + c + 0] = tf32r(wvr[i].x); ws[r][128 + c + 1] = tf32r(wvr[i].y);
            ws[r][128 + c + 2] = tf32r(wvr[i].z); ws[r][128 + c + 3] = tf32r(wvr[i].w);
        }
        __syncthreads();

        if (k0 + 32 < DD) {
            int kn = k0 + 32;
            #pragma unroll
            for (int i = 0; i < 4; i++) {
                int idx = tid + i * 256;
                int r = idx >> 3;
                int q = idx & 7;
                xr[i] = *(const float4*)&x[(size_t)(row0 + r) * DD + kn + q * 4];
            }
            #pragma unroll
            for (int i = 0; i < 2; i++) {
                int idx = tid + i * 256;
                int r = idx >> 4;
                int q = idx & 15;
                wqr[i] = *(const float4*)&Wq[(size_t)(kn + r) * HD + q * 4];
                wkr[i] = *(const float4*)&Wk[(size_t)(kn + r) * HD + q * 4];
                wvr[i] = *(const float4*)&Wv[(size_t)(kn + r) * HD + q * 4];
            }
        }

        #pragma unroll
        for (int kk = 0; kk < 4; kk++) {
            int kb = kk * 8;
            unsigned a[2][4];
            #pragma unroll
            for (int h = 0; h < 2; h++) {
                int rr = wm * 32 + h * 16 + g;
                a[h][0] = __float_as_uint(xs[rr][kb + t]);
                a[h][1] = __float_as_uint(xs[rr + 8][kb + t]);
                a[h][2] = __float_as_uint(xs[rr][kb + t + 4]);
                a[h][3] = __float_as_uint(xs[rr + 8][kb + t + 4]);
            }
            #pragma unroll
            for (int n = 0; n < 12; n++) {
                int nc = wn * 96 + n * 8;
                unsigned b0 = __float_as_uint(ws[kb + t][nc + g]);
                unsigned b1 = __float_as_uint(ws[kb + t + 4][nc + g]);
                mma8(acc[0][n], a[0][0], a[0][1], a[0][2], a[0][3], b0, b1);
                mma8(acc[1][n], a[1][0], a[1][1], a[1][2], a[1][3], b0, b1);
            }
        }
        __syncthreads();
    }

    #pragma unroll
    for (int h = 0; h < 2; h++) {
        int r0 = row0 + wm * 32 + h * 16 + g;
        #pragma unroll
        for (int n = 0; n < 12; n++) {
            int nc = wn * 96 + n * 8;
            int mat = nc >> 6;
            int lc = (nc & 63) + 2 * t;
            #pragma unroll
            for (int hh = 0; hh < 2; hh++) {
                int r = r0 + hh * 8;
                float v0 = acc[h][n][hh * 2 + 0];
                float v1 = acc[h][n][hh * 2 + 1];
                if (mat == 0) {
                    float2 o = make_float2(tf32r(v0 * SCALE_Q), tf32r(v1 * SCALE_Q));
                    *(float2*)&g_q[(size_t)r * HD + lc] = o;
                } else {
                    int b = r >> 11;
                    int rr = r & 2047;
                    float2 o = make_float2(tf32r(v0), tf32r(v1));
                    if (mat == 1) *(float2*)&g_k[((size_t)b * SSZ + rr) * HD + lc] = o;
                    else          *(float2*)&g_v[((size_t)b * SSZ + rr) * HD + lc] = o;
                }
            }
        }
    }
}

// ---------------------------------------------------------------------------
// Kernel 3: flash attention v5 — column-split warp pairs.
// 256 threads, 8 warps: warp w = row-group (w>>1, 32 rows) x col-half (w&1,
// 32 of 64 keys). Total smem K/V traffic identical to the proven R12 layout,
// but 2 warps/SMSP hide LDS/HMMA latency. Per-thread regs ~130 (sc 32 +
// acc 32). Softmax merges row max/sum across the warp pair via smem
// (mxs/lss) with 2 extra barriers per tile; m/l replicated in both warps.
// Q read from smem each tile (as R12); P written per-half, read cross-half
// after the merge barrier.
// ---------------------------------------------------------------------------
#define TP2 68                               // stride = 4 (mod 32)
#define KVB (64 * TP2)                       // one K or V buffer (floats)
#define ATTN_SMEM_FLOATS (2 * 128 * TP2 + 4 * KVB + 512)
#define ATTN_SMEM_BYTES  (ATTN_SMEM_FLOATS * 4)

__global__ __launch_bounds__(256, 1) void attn_kernel(float* __restrict__ out) {
    extern __shared__ float sm[];
    float* qs  = sm;                         // [128][TP2] Q (persistent)
    float* ps  = sm + 128 * TP2;             // [128][TP2] P (pair-shared rows)
    float* ks  = sm + 2 * 128 * TP2;         // 2 x [64][TP2]
    float* vs  = ks + 2 * KVB;               // 2 x [64][TP2]
    float* mxs = vs + 2 * KVB;               // [128][2] row-max partials
    float* lss = mxs + 256;                  // [128][2] row-sum partials

    int tid = threadIdx.x;
    int lane = tid & 31;
    int w = tid >> 5;
    int wm = w >> 1;                         // row group (32 rows)
    int ch = w & 1;                          // column half (32 keys)
    int g = lane >> 2;
    int t = lane & 3;
    int b = blockIdx.y;
    int q0 = blockIdx.x * 128;
    int r0 = wm * 32;

    // Prologue: async-load K/V tile 0 into buffer 0
    #pragma unroll
    for (int it = 0; it < 4; it++) {
        int idx = tid + it * 256;
        int r = idx >> 4;
        int q = idx & 15;
        size_t src = ((size_t)b * SSZ + r) * HD + q * 4;
        cp16(ks + r * TP2 + q * 4, &g_k[src]);
        cp16(vs + r * TP2 + q * 4, &g_v[src]);
    }
    CP_COMMIT();

    // Stage Q 128x64 (coalesced)
    #pragma unroll
    for (int i = 0; i < 8; i++) {
        int idx = tid + i * 256;
        int r = idx >> 4;
        int q = idx & 15;
        float4 v = *(const float4*)&g_q[((size_t)b * TT + q0 + r) * HD + q * 4];
        *(float4*)&qs[r * TP2 + q * 4] = v;
    }

    // Row stats (replicated in both warps of a pair):
    // index 2h   -> row r0 + h*16 + g
    // index 2h+1 -> row r0 + h*16 + g + 8
    float m[4] = {-1e30f, -1e30f, -1e30f, -1e30f};
    float l[4] = {0.0f, 0.0f, 0.0f, 0.0f};
    float acc[2][4][4];
    #pragma unroll
    for (int h = 0; h < 2; h++)
        #pragma unroll
        for (int n = 0; n < 4; n++)
            #pragma unroll
            for (int i = 0; i < 4; i++) acc[h][n][i] = 0.0f;

    for (int ti = 0; ti < 33; ti++) {
        CP_WAIT0();
        __syncthreads();   // tile ti visible; prev iter phase C done

        if (ti < 32) {
            int s0 = (ti + 1) * 64;
            float* kb_ = ks + ((ti + 1) & 1) * KVB;
            float* vb_ = vs + ((ti + 1) & 1) * KVB;
            #pragma unroll
            for (int it = 0; it < 4; it++) {
                int idx = tid + it * 256;
                int r = idx >> 4;
                int q = idx & 15;
                size_t src = ((size_t)b * SSZ + s0 + r) * HD + q * 4;
                cp16(kb_ + r * TP2 + q * 4, &g_k[src]);
                cp16(vb_ + r * TP2 + q * 4, &g_v[src]);
            }
            CP_COMMIT();
        }

        const float* kcur = ks + (ti & 1) * KVB;
        const float* vcur = vs + (ti & 1) * KVB;

        // Phase A: S = Q * K^T (warp: 32 rows x its 32-key half)
        float sc[2][4][4];
        #pragma unroll
        for (int h = 0; h < 2; h++)
            #pragma unroll
            for (int n = 0; n < 4; n++)
                #pragma unroll
                for (int i = 0; i < 4; i++) sc[h][n][i] = 0.0f;
        #pragma unroll
        for (int kk = 0; kk < 8; kk++) {
            int kb = kk * 8;
            unsigned a[2][4];
            #pragma unroll
            for (int h = 0; h < 2; h++) {
                int rr = r0 + h * 16 + g;
                a[h][0] = __float_as_uint(qs[rr * TP2 + kb + t]);
                a[h][1] = __float_as_uint(qs[(rr + 8) * TP2 + kb + t]);
                a[h][2] = __float_as_uint(qs[rr * TP2 + kb + t + 4]);
                a[h][3] = __float_as_uint(qs[(rr + 8) * TP2 + kb + t + 4]);
            }
            #pragma unroll
            for (int n = 0; n < 4; n++) {
                int key = ch * 32 + n * 8 + g;
                unsigned b0 = __float_as_uint(kcur[key * TP2 + kb + t]);
                unsigned b1 = __float_as_uint(kcur[key * TP2 + kb + t + 4]);
                mma8(sc[0][n], a[0][0], a[0][1], a[0][2], a[0][3], b0, b1);
                mma8(sc[1][n], a[1][0], a[1][1], a[1][2], a[1][3], b0, b1);
            }
        }

        // Half-row max -> smem partials
        float mx[4] = {-1e30f, -1e30f, -1e30f, -1e30f};
        #pragma unroll
        for (int h = 0; h < 2; h++)
            #pragma unroll
            for (int n = 0; n < 4; n++) {
                mx[2 * h]     = fmaxf(mx[2 * h],     fmaxf(sc[h][n][0], sc[h][n][1]));
                mx[2 * h + 1] = fmaxf(mx[2 * h + 1], fmaxf(sc[h][n][2], sc[h][n][3]));
            }
        #pragma unroll
        for (int i = 0; i < 4; i++) {
            mx[i] = fmaxf(mx[i], __shfl_xor_sync(0xffffffffu, mx[i], 1));
            mx[i] = fmaxf(mx[i], __shfl_xor_sync(0xffffffffu, mx[i], 2));
        }
        if (t == 0) {
            #pragma unroll
            for (int h = 0; h < 2; h++) {
                mxs[(r0 + h * 16 + g) * 2 + ch]     = mx[2 * h];
                mxs[(r0 + h * 16 + g + 8) * 2 + ch] = mx[2 * h + 1];
            }
        }
        __syncthreads();

        // Merge maxes, exponentiate, write P + sum partials, rescale acc
        float fs[4];
        #pragma unroll
        for (int h = 0; h < 2; h++) {
            int rowA = r0 + h * 16 + g;
            int rowB = rowA + 8;
            float mnA = fmaxf(m[2 * h],     fmaxf(mxs[rowA * 2], mxs[rowA * 2 + 1]));
            float mnB = fmaxf(m[2 * h + 1], fmaxf(mxs[rowB * 2], mxs[rowB * 2 + 1]));
            float fA = exp2a(m[2 * h] - mnA);
            float fB = exp2a(m[2 * h + 1] - mnB);
            float sA = 0.0f, sB = 0.0f;
            #pragma unroll
            for (int n = 0; n < 4; n++) {
                sc[h][n][0] = tf32r(exp2a(sc[h][n][0] - mnA)); sA += sc[h][n][0];
                sc[h][n][1] = tf32r(exp2a(sc[h][n][1] - mnA)); sA += sc[h][n][1];
                sc[h][n][2] = tf32r(exp2a(sc[h][n][2] - mnB)); sB += sc[h][n][2];
                sc[h][n][3] = tf32r(exp2a(sc[h][n][3] - mnB)); sB += sc[h][n][3];
            }
            sA += __shfl_xor_sync(0xffffffffu, sA, 1);
            sA += __shfl_xor_sync(0xffffffffu, sA, 2);
            sB += __shfl_xor_sync(0xffffffffu, sB, 1);
            sB += __shfl_xor_sync(0xffffffffu, sB, 2);
            if (t == 0) {
                lss[rowA * 2 + ch] = sA;
                lss[rowB * 2 + ch] = sB;
            }
            #pragma unroll
            for (int n = 0; n < 4; n++) {
                acc[h][n][0] *= fA; acc[h][n][1] *= fA;
                acc[h][n][2] *= fB; acc[h][n][3] *= fB;
            }
            #pragma unroll
            for (int n = 0; n < 4; n++) {
                int col = ch * 32 + n * 8 + 2 * t;
                *(float2*)&ps[rowA * TP2 + col] = make_float2(sc[h][n][0], sc[h][n][1]);
                *(float2*)&ps[rowB * TP2 + col] = make_float2(sc[h][n][2], sc[h][n][3]);
            }
            m[2 * h] = mnA; m[2 * h + 1] = mnB;
            fs[2 * h] = fA; fs[2 * h + 1] = fB;
        }
        __syncthreads();

        // Merge sums (both warps compute identical l updates)
        #pragma unroll
        for (int h = 0; h < 2; h++) {
            int rowA = r0 + h * 16 + g;
            int rowB = rowA + 8;
            l[2 * h]     = l[2 * h]     * fs[2 * h]     + lss[rowA * 2] + lss[rowA * 2 + 1];
            l[2 * h + 1] = l[2 * h + 1] * fs[2 * h + 1] + lss[rowB * 2] + lss[rowB * 2 + 1];
        }

        // Phase C: O += P * V (A = full 64-col P rows, B = V col-half)
        #pragma unroll
        for (int kk = 0; kk < 8; kk++) {
            int kb = kk * 8;
            unsigned a[2][4];
            #pragma unroll
            for (int h = 0; h < 2; h++) {
                int rr = r0 + h * 16 + g;
                a[h][0] = __float_as_uint(ps[rr * TP2 + kb + t]);
                a[h][1] = __float_as_uint(ps[(rr + 8) * TP2 + kb + t]);
                a[h][2] = __float_as_uint(ps[rr * TP2 + kb + t + 4]);
                a[h][3] = __float_as_uint(ps[(rr + 8) * TP2 + kb + t + 4]);
            }
            #pragma unroll
            for (int n = 0; n < 4; n++) {
                int col = ch * 32 + n * 8 + g;
                unsigned b0 = __float_as_uint(vcur[(kb + t) * TP2 + col]);
                unsigned b1 = __float_as_uint(vcur[(kb + t + 4) * TP2 + col]);
                mma8(acc[0][n], a[0][0], a[0][1], a[0][2], a[0][3], b0, b1);
                mma8(acc[1][n], a[1][0], a[1][1], a[1][2], a[1][3], b0, b1);
            }
        }
        // next-iter loop-top barrier guards K/V buffer and P reuse
    }

    // Epilogue: normalize by l and store (each warp writes its col-half)
    #pragma unroll
    for (int h = 0; h < 2; h++) {
        int ra = q0 + r0 + h * 16 + g;
        int rb = ra + 8;
        float ia = 1.0f / l[2 * h];
        float ib = 1.0f / l[2 * h + 1];
        #pragma unroll
        for (int n = 0; n < 4; n++) {
            int col = ch * 32 + n * 8 + 2 * t;
            *(float2*)&out[((size_t)b * TT + ra) * HD + col] =
                make_float2(acc[h][n][0] * ia, acc[h][n][1] * ia);
            *(float2*)&out[((size_t)b * TT + rb) * HD + col] =
                make_float2(acc[h][n][2] * ib, acc[h][n][3] * ib);
        }
    }
}

// ---------------------------------------------------------------------------
extern "C" void kernel_launch(void* const* d_in, const int* in_sizes, int n_in,
                              void* d_out, int out_size) {
    const float* x      = (const float*)d_in[0];  // [8,2048,1024]
    const float* c_emb  = (const float*)d_in[1];  // [64,64]
    const float* Wq     = (const float*)d_in[2];  // [1024,64]
    const float* Wk     = (const float*)d_in[3];
    const float* Wv     = (const float*)d_in[4];
    const float* gamma  = (const float*)d_in[5];  // [64]
    const float* beta   = (const float*)d_in[6];  // [64]
    float* out          = (float*)d_out;          // [8,2048,64]

    (void)in_sizes; (void)n_in; (void)out_size;

    cudaFuncSetAttribute(attn_kernel,
                         cudaFuncAttributeMaxDynamicSharedMemorySize,
                         ATTN_SMEM_BYTES);

    ln_kernel<<<MM, 64>>>(c_emb, gamma, beta);
    qkv_kernel<<<BT / 128, 256>>>(x, Wq, Wk, Wv);
    dim3 agrid(TT / 128, BB);
    attn_kernel<<<agrid, 256, ATTN_SMEM_BYTES>>>(out);
}